// round 8
// baseline (speedup 1.0000x reference)
#include <cuda_runtime.h>
#include <cstdint>

// B=8, S=512, V=32000, D=4096, r=16, E=4
#define TOKS   4096
#define SLEN   512
#define SPLITL 32
#define DDIM   4096
#define VDIM   32000
#define SCALE  2.0f   // lora_alpha / r

#define TTOK   32     // tokens per tile
#define TD     512    // d per tile (128 threads * d-span 4)
#define CPAD   36     // padded c-row stride in floats

typedef unsigned long long u64;

__device__ __forceinline__ void upk2(u64 v, float& lo, float& hi) {
    asm("mov.b64 {%0, %1}, %2;" : "=f"(lo), "=f"(hi) : "l"(v));
}
__device__ __forceinline__ void fma2(u64& acc, u64 a, u64 b) {
    asm("fma.rn.f32x2 %0, %1, %2, %0;" : "+l"(acc) : "l"(a), "l"(b));
}

// ---------------------------------------------------------------------------
// Grid (128 token-tiles, 8 d-tiles) = 1024 CTAs, 128 threads, 3 CTAs/SM.
// Thread owns 4 consecutive d's; k packed PAIRWISE into f32x2. B pairs
// {B[d,2j],B[d,2j+1]} are raw contiguous row loads (128 regs). One
// accumulator per d (dependent fma2 4 instrs apart = 8 cyc >= 4-cyc lat).
// Per warp-token: 8 broadcast LDS.128 -> 64 fma2 -> 128 outputs.
// Base gather: 4-slot register ring (LDG.128), consumed in place.
// c-phase: each warp computes one k-octet for all 32 tokens.
// int64/int32 x detection: odd words of first 256 x-words all zero <=> int64.
// ---------------------------------------------------------------------------
__global__ __launch_bounds__(128, 3) void fused_k(
    const int*   __restrict__ xw,
    const float* __restrict__ emb,
    const float* __restrict__ A1, const float* __restrict__ B1,
    const float* __restrict__ A2, const float* __restrict__ B2,
    const float* __restrict__ Wi, const float* __restrict__ bi,
    const float* __restrict__ Wt, const float* __restrict__ bt,
    float* __restrict__ out)
{
    __shared__ __align__(16) float scf[TTOK * CPAD];   // c[t][k]
    __shared__ int      stok[TTOK];
    __shared__ unsigned sdet[4];

    const int tid   = threadIdx.x;
    const int ttile = blockIdx.x;
    const int d0    = blockIdx.y * TD + tid * 4;

    // --- dtype detect ---
    {
        int hiw = xw[2 * tid + 1];                    // words 1..255, in-bounds both ways
        unsigned ball = __ballot_sync(0xffffffffu, hiw != 0);
        if ((tid & 31) == 0) sdet[tid >> 5] = ball;
    }

    // --- B rows for d0..d0+3 straight into u64 k-pairs (16 per d) ---
    u64 Bp[4][16];
#pragma unroll
    for (int dd = 0; dd < 4; dd++) {
        const ulonglong2* r1 = (const ulonglong2*)(B1 + (size_t)(d0 + dd) * 16);
        const ulonglong2* r2 = (const ulonglong2*)(B2 + (size_t)(d0 + dd) * 16);
#pragma unroll
        for (int q = 0; q < 4; q++) {
            ulonglong2 v = r1[q];
            Bp[dd][2 * q] = v.x; Bp[dd][2 * q + 1] = v.y;
        }
#pragma unroll
        for (int q = 0; q < 4; q++) {
            ulonglong2 v = r2[q];
            Bp[dd][8 + 2 * q] = v.x; Bp[dd][8 + 2 * q + 1] = v.y;
        }
    }
    __syncthreads();                                   // sdet visible

    // --- c phase: warp w computes k-octet w for all 32 tokens ---
    {
        const bool is64 = ((sdet[0] | sdet[1] | sdet[2] | sdet[3]) == 0);
        const int  w    = tid >> 5;                    // 0..3
        const int  t    = tid & 31;                    // token within tile
        const int  i    = ttile * TTOK + t;
        const int  tok  = is64 ? xw[2 * i] : xw[i];
        if (w == 0) stok[t] = tok;
        const int s = i & (SLEN - 1);
        const float* W = (s < SPLITL) ? Wi : Wt;
        const float* b = (s < SPLITL) ? bi : bt;
        float l0 = W[tok] + b[0];
        float l1 = W[VDIM + tok] + b[1];
        float w0 = 1.0f / (1.0f + expf(l1 - l0));
        // warps 0,1 -> A1 scaled by w0*SCALE (k 0..15); warps 2,3 -> A2 (k 16..31)
        float sA = (w < 2) ? (w0 * SCALE) : (SCALE - w0 * SCALE);
        const float* Am = (w < 2) ? A1 : A2;
        const int r0 = (w & 1) * 8;                    // row offset within matrix
        float c[8];
#pragma unroll
        for (int r = 0; r < 8; r++) c[r] = sA * Am[(size_t)(r0 + r) * VDIM + tok];
        float4* dst = (float4*)(scf + t * CPAD + w * 8);
        dst[0] = make_float4(c[0], c[1], c[2], c[3]);
        dst[1] = make_float4(c[4], c[5], c[6], c[7]);
    }
    __syncthreads();                                   // scf + stok visible

    // --- main loop over 32 tokens; 4-slot LDG.128 ring, consumed in place ---
    const size_t ob = (size_t)(ttile * TTOK) * DDIM + d0;
    float4 pf[4];
#pragma unroll
    for (int j = 0; j < 4; j++)
        pf[j] = __ldg((const float4*)(emb + (size_t)stok[j] * DDIM + d0));

#pragma unroll 4
    for (int t = 0; t < TTOK; t++) {
        const float4 bv = pf[t & 3];
        if (t + 4 < TTOK)
            pf[t & 3] = __ldg((const float4*)(emb + (size_t)stok[t + 4] * DDIM + d0));

        const ulonglong2* cr = (const ulonglong2*)(scf + t * CPAD);
        u64 a0 = 0, a1 = 0, a2 = 0, a3 = 0;
#pragma unroll
        for (int jj = 0; jj < 8; jj++) {
            ulonglong2 cc = cr[jj];                    // LDS.128 broadcast
            fma2(a0, Bp[0][2 * jj],     cc.x);
            fma2(a1, Bp[1][2 * jj],     cc.x);
            fma2(a2, Bp[2][2 * jj],     cc.x);
            fma2(a3, Bp[3][2 * jj],     cc.x);
            fma2(a0, Bp[0][2 * jj + 1], cc.y);
            fma2(a1, Bp[1][2 * jj + 1], cc.y);
            fma2(a2, Bp[2][2 * jj + 1], cc.y);
            fma2(a3, Bp[3][2 * jj + 1], cc.y);
        }
        float l0, h0, l1, h1, l2, h2, l3, h3;
        upk2(a0, l0, h0);
        upk2(a1, l1, h1);
        upk2(a2, l2, h2);
        upk2(a3, l3, h3);
        float4 o;
        o.x = bv.x + (l0 + h0);
        o.y = bv.y + (l1 + h1);
        o.z = bv.z + (l2 + h2);
        o.w = bv.w + (l3 + h3);
        __stcs((float4*)(out + ob + (size_t)t * DDIM), o);
    }
}

// ---------------------------------------------------------------------------
extern "C" void kernel_launch(void* const* d_in, const int* in_sizes, int n_in,
                              void* d_out, int out_size) {
    const int*   x   = (const int*)d_in[0];
    const float* emb = (const float*)d_in[1];
    const float* A1  = (const float*)d_in[2];
    const float* B1  = (const float*)d_in[3];
    const float* A2  = (const float*)d_in[4];
    const float* B2  = (const float*)d_in[5];
    const float* Wi  = (const float*)d_in[6];
    const float* bi  = (const float*)d_in[7];
    const float* Wt  = (const float*)d_in[8];
    const float* bt  = (const float*)d_in[9];
    float* out = (float*)d_out;

    fused_k<<<dim3(TOKS / TTOK, DDIM / TD), 128>>>(
        x, emb, A1, B1, A2, B2, Wi, bi, Wt, bt, out);
}

// round 9
// speedup vs baseline: 1.6843x; 1.6843x over previous
#include <cuda_runtime.h>
#include <cuda_bf16.h>
#include <cstdint>

// B=8, S=512, V=32000, D=4096, r=16, E=4
#define TOKS   4096
#define SLEN   512
#define SPLITL 32
#define DDIM   4096
#define VDIM   32000
#define SCALE  2.0f   // lora_alpha / r

#define TTOK   64     // tokens per CTA (4 m-tiles of 16)
#define TD     256    // d per CTA (4 warps * 64)
#define CROW   80     // c-tile row stride in bytes (16B-aligned, LDSM conflict-free)

__device__ __forceinline__ uint32_t s2u(const void* p) {
    uint32_t a;
    asm("{ .reg .u64 t; cvta.to.shared.u64 t, %1; cvt.u32.u64 %0, t; }"
        : "=r"(a) : "l"(p));
    return a;
}
// pack two f32 into bf16x2: lo -> element 0 (low 16 bits), hi -> element 1
__device__ __forceinline__ uint32_t cvt2(float hi, float lo) {
    uint32_t r;
    asm("cvt.rn.bf16x2.f32 %0, %1, %2;" : "=r"(r) : "f"(hi), "f"(lo));
    return r;
}
__device__ __forceinline__ void mma16816(
    float& d0, float& d1, float& d2, float& d3,
    uint32_t a0, uint32_t a1, uint32_t a2, uint32_t a3,
    uint32_t b0, uint32_t b1)
{
    asm volatile(
        "mma.sync.aligned.m16n8k16.row.col.f32.bf16.bf16.f32 "
        "{%0,%1,%2,%3}, {%4,%5,%6,%7}, {%8,%9}, {%0,%1,%2,%3};"
        : "+f"(d0), "+f"(d1), "+f"(d2), "+f"(d3)
        : "r"(a0), "r"(a1), "r"(a2), "r"(a3), "r"(b0), "r"(b1));
}

// ---------------------------------------------------------------------------
// Grid (64 token-tiles, 16 d-tiles) = 1024 CTAs, 128 threads (4 warps), 3/SM.
// delta[tok][d] = sum_k c[tok][k] * Wcat[d][k] done as mma.sync m16n8k16 bf16:
//   A (c tile, 64x32 bf16) lives in smem (80B row stride, conflict-free LDSM),
//   B frags built per-lane straight from B1/B2 global (contiguous float2 ->
//   cvt bf16x2), 8 n-tiles x 2 k-steps = 32 regs, persistent.
// Epilogue: gathered base row (16 LDG.64 prefetched, MLP 16) + STG.64 stream.
// c-phase: threads 0-63 -> A1*(w0*SCALE) (k 0..15), 64-127 -> A2 (k 16..31).
// int64/int32 x detection: odd words of first 256 x-words all zero <=> int64.
// ---------------------------------------------------------------------------
__global__ __launch_bounds__(128, 3) void fused_k(
    const int*   __restrict__ xw,
    const float* __restrict__ emb,
    const float* __restrict__ A1, const float* __restrict__ B1,
    const float* __restrict__ A2, const float* __restrict__ B2,
    const float* __restrict__ Wi, const float* __restrict__ bi,
    const float* __restrict__ Wt, const float* __restrict__ bt,
    float* __restrict__ out)
{
    __shared__ __align__(16) unsigned char cA[TTOK * CROW];  // c tile, bf16
    __shared__ int      stok[TTOK];
    __shared__ unsigned sdet[4];

    const int tid   = threadIdx.x;
    const int lane  = tid & 31;
    const int w     = tid >> 5;
    const int ttile = blockIdx.x;
    const int dwarp = blockIdx.y * TD + w * 64;   // this warp's 64 d-columns

    // --- dtype detect ---
    {
        int hiw = xw[2 * tid + 1];                // words 1..255, in-bounds both ways
        unsigned ball = __ballot_sync(0xffffffffu, hiw != 0);
        if (lane == 0) sdet[w] = ball;
    }

    // --- B fragments straight from global: lane owns (col = lane/4, k-pair = lane%4) ---
    // bA[nt] = B1 (k 0..15), bB[nt] = B2 (k 16..31); [0] = k-low 8, [1] = k-high 8
    uint32_t bA[8][2], bB[8][2];
    {
        const int dcol = lane >> 2;
        const int kk   = 2 * (lane & 3);
#pragma unroll
        for (int nt = 0; nt < 8; nt++) {
            const float* p1 = B1 + (size_t)(dwarp + nt * 8 + dcol) * 16 + kk;
            const float* p2 = B2 + (size_t)(dwarp + nt * 8 + dcol) * 16 + kk;
            float2 lo1 = __ldg((const float2*)p1);
            float2 hi1 = __ldg((const float2*)(p1 + 8));
            float2 lo2 = __ldg((const float2*)p2);
            float2 hi2 = __ldg((const float2*)(p2 + 8));
            bA[nt][0] = cvt2(lo1.y, lo1.x);
            bA[nt][1] = cvt2(hi1.y, hi1.x);
            bB[nt][0] = cvt2(lo2.y, lo2.x);
            bB[nt][1] = cvt2(hi2.y, hi2.x);
        }
    }
    __syncthreads();                              // sdet visible

    // --- c phase: half 0 -> A1 (k 0..15), half 1 -> A2 (k 16..31) ---
    {
        const bool is64 = ((sdet[0] | sdet[1] | sdet[2] | sdet[3]) == 0);
        const int  half = tid >> 6;
        const int  t    = tid & 63;
        const int  i    = ttile * TTOK + t;
        const int  tok  = is64 ? xw[2 * i] : xw[i];
        if (half == 0) stok[t] = tok;
        const int s = i & (SLEN - 1);
        const float* W = (s < SPLITL) ? Wi : Wt;
        const float* b = (s < SPLITL) ? bi : bt;
        float l0 = W[tok] + b[0];
        float l1 = W[VDIM + tok] + b[1];
        float w0 = 1.0f / (1.0f + expf(l1 - l0));
        float sA = half ? (SCALE - w0 * SCALE) : (w0 * SCALE);
        const float* Am = half ? A2 : A1;
        float c[16];
#pragma unroll
        for (int r = 0; r < 16; r++) c[r] = sA * Am[(size_t)r * VDIM + tok];
        uint32_t u[8];
#pragma unroll
        for (int j = 0; j < 8; j++) u[j] = cvt2(c[2 * j + 1], c[2 * j]);
        uint4* dst = (uint4*)(cA + t * CROW + half * 32);
        dst[0] = make_uint4(u[0], u[1], u[2], u[3]);
        dst[1] = make_uint4(u[4], u[5], u[6], u[7]);
    }
    __syncthreads();                              // cA + stok visible

    // --- main: 4 m-tiles of 16 tokens ---
    const uint32_t cAu   = s2u(cA);
    const size_t   obase = (size_t)(ttile * TTOK) * DDIM;
    const int      ccol  = 2 * (lane & 3);

#pragma unroll 1
    for (int mt = 0; mt < 4; mt++) {
        // token rows this lane touches in the D fragment
        const int tr0  = mt * 16 + (lane >> 2);
        const int tr1  = tr0 + 8;
        const int tok0 = stok[tr0];
        const int tok1 = stok[tr1];

        // base prefetch: 16 LDG.64, long latency covered by LDSM+MMA below
        float2 bs0[8], bs1[8];
        {
            const float* e0 = emb + (size_t)tok0 * DDIM + dwarp + ccol;
            const float* e1 = emb + (size_t)tok1 * DDIM + dwarp + ccol;
#pragma unroll
            for (int nt = 0; nt < 8; nt++) {
                bs0[nt] = __ldg((const float2*)(e0 + nt * 8));
                bs1[nt] = __ldg((const float2*)(e1 + nt * 8));
            }
        }

        // A fragments: 2x ldmatrix.x4 (k-step 0 at +0, k-step 1 at +32B)
        uint32_t a0, a1, a2, a3, a4, a5, a6, a7;
        {
            uint32_t ad = cAu + (uint32_t)(mt * 16 + (lane & 15)) * CROW
                        + ((lane >> 4) << 4);
            asm volatile("ldmatrix.sync.aligned.m8n8.x4.shared.b16 {%0,%1,%2,%3}, [%4];"
                         : "=r"(a0), "=r"(a1), "=r"(a2), "=r"(a3) : "r"(ad));
            asm volatile("ldmatrix.sync.aligned.m8n8.x4.shared.b16 {%0,%1,%2,%3}, [%4];"
                         : "=r"(a4), "=r"(a5), "=r"(a6), "=r"(a7) : "r"(ad + 32));
        }

        // 8 n-tiles: 2 mma each (k-step 0 = B1, k-step 1 = B2), then epilogue
#pragma unroll
        for (int nt = 0; nt < 8; nt++) {
            float d0 = 0.f, d1 = 0.f, d2 = 0.f, d3 = 0.f;
            mma16816(d0, d1, d2, d3, a0, a1, a2, a3, bA[nt][0], bA[nt][1]);
            mma16816(d0, d1, d2, d3, a4, a5, a6, a7, bB[nt][0], bB[nt][1]);
            float2 o0 = make_float2(bs0[nt].x + d0, bs0[nt].y + d1);
            float2 o1 = make_float2(bs1[nt].x + d2, bs1[nt].y + d3);
            const size_t oc = dwarp + ccol + nt * 8;
            __stcs((float2*)(out + obase + (size_t)tr0 * DDIM + oc), o0);
            __stcs((float2*)(out + obase + (size_t)tr1 * DDIM + oc), o1);
        }
    }
}

// ---------------------------------------------------------------------------
extern "C" void kernel_launch(void* const* d_in, const int* in_sizes, int n_in,
                              void* d_out, int out_size) {
    const int*   x   = (const int*)d_in[0];
    const float* emb = (const float*)d_in[1];
    const float* A1  = (const float*)d_in[2];
    const float* B1  = (const float*)d_in[3];
    const float* A2  = (const float*)d_in[4];
    const float* B2  = (const float*)d_in[5];
    const float* Wi  = (const float*)d_in[6];
    const float* bi  = (const float*)d_in[7];
    const float* Wt  = (const float*)d_in[8];
    const float* bt  = (const float*)d_in[9];
    float* out = (float*)d_out;

    fused_k<<<dim3(TOKS / TTOK, DDIM / TD), 128>>>(
        x, emb, A1, B1, A2, B2, Wi, bi, Wt, bt, out);
}

// round 10
// speedup vs baseline: 1.8531x; 1.1002x over previous
#include <cuda_runtime.h>
#include <cuda_bf16.h>
#include <cstdint>

// B=8, S=512, V=32000, D=4096, r=16, E=4
#define TOKS   4096
#define SLEN   512
#define SPLITL 32
#define DDIM   4096
#define VDIM   32000
#define SCALE  2.0f   // lora_alpha / r

#define TTOK   64     // tokens per CTA (4 m-tiles of 16)
#define TD     256    // d per CTA (4 warps * 64)
#define CROW   80     // c-tile row stride in bytes (16B-aligned, LDSM conflict-free)

__device__ __forceinline__ uint32_t s2u(const void* p) {
    uint32_t a;
    asm("{ .reg .u64 t; cvta.to.shared.u64 t, %1; cvt.u32.u64 %0, t; }"
        : "=r"(a) : "l"(p));
    return a;
}
// pack two f32 into bf16x2: lo -> low 16 bits, hi -> high
__device__ __forceinline__ uint32_t cvt2(float hi, float lo) {
    uint32_t r;
    asm("cvt.rn.bf16x2.f32 %0, %1, %2;" : "=r"(r) : "f"(hi), "f"(lo));
    return r;
}
__device__ __forceinline__ void mma16816(
    float& d0, float& d1, float& d2, float& d3,
    uint32_t a0, uint32_t a1, uint32_t a2, uint32_t a3,
    uint32_t b0, uint32_t b1)
{
    asm volatile(
        "mma.sync.aligned.m16n8k16.row.col.f32.bf16.bf16.f32 "
        "{%0,%1,%2,%3}, {%4,%5,%6,%7}, {%8,%9}, {%0,%1,%2,%3};"
        : "+f"(d0), "+f"(d1), "+f"(d2), "+f"(d3)
        : "r"(a0), "r"(a1), "r"(a2), "r"(a3), "r"(b0), "r"(b1));
}

// ---------------------------------------------------------------------------
// Grid (64 token-tiles, 16 d-tiles) = 1024 CTAs, 128 threads (4 warps), 4/SM.
// delta = C[64x32]·Wcat[32x256]^T via mma.sync m16n8k16 bf16 (f32 accum).
// B-fragment column remap: mma tiles are paired (X,Y) over 16 global cols with
//   gX(c) = 4*(c>>1) + (c&1),  gY(c) = gX(c) + 2
// so each lane's D outputs from X and Y form 4 CONTIGUOUS floats -> the
// epilogue gather/store is float4 (8 LDG.128 + 8 STG.128 per warp-mtile,
// half the L1 instructions of the n-linear map). B frags built per-lane
// straight from B1/B2 global rows (contiguous float2 -> bf16x2), 32 regs.
// c-phase: threads 0-63 -> A1*(w0*SCALE) (k 0..15), 64-127 -> A2 (k 16..31).
// int64/int32 x detection: odd words of first 256 x-words all zero <=> int64.
// ---------------------------------------------------------------------------
__global__ __launch_bounds__(128, 4) void fused_k(
    const int*   __restrict__ xw,
    const float* __restrict__ emb,
    const float* __restrict__ A1, const float* __restrict__ B1,
    const float* __restrict__ A2, const float* __restrict__ B2,
    const float* __restrict__ Wi, const float* __restrict__ bi,
    const float* __restrict__ Wt, const float* __restrict__ bt,
    float* __restrict__ out)
{
    __shared__ __align__(16) unsigned char cA[TTOK * CROW];  // c tile, bf16
    __shared__ int      stok[TTOK];
    __shared__ unsigned sdet[4];

    const int tid   = threadIdx.x;
    const int lane  = tid & 31;
    const int w     = tid >> 5;
    const int ttile = blockIdx.x;
    const int dwarp = blockIdx.y * TD + w * 64;   // this warp's 64 d-columns

    // --- dtype detect ---
    {
        int hiw = xw[2 * tid + 1];                // words 1..255, in-bounds both ways
        unsigned ball = __ballot_sync(0xffffffffu, hiw != 0);
        if (lane == 0) sdet[w] = ball;
    }

    // --- B fragments with remapped columns ---
    // lane's fragment column n = lane>>2; tile (st, t): gcol = st*16 + 4*(n>>1) + 2*t + (n&1)
    // b1f = B1 (k 0..15), b2f = B2 (k 16..31); last index: k-low 8 / k-high 8
    uint32_t b1f[4][2][2], b2f[4][2][2];
    {
        const int n  = lane >> 2;
        const int kk = 2 * (lane & 3);
#pragma unroll
        for (int st = 0; st < 4; st++) {
#pragma unroll
            for (int t = 0; t < 2; t++) {
                const int gcol = dwarp + st * 16 + 4 * (n >> 1) + 2 * t + (n & 1);
                const float* p1 = B1 + (size_t)gcol * 16 + kk;
                const float* p2 = B2 + (size_t)gcol * 16 + kk;
                float2 lo1 = __ldg((const float2*)p1);
                float2 hi1 = __ldg((const float2*)(p1 + 8));
                float2 lo2 = __ldg((const float2*)p2);
                float2 hi2 = __ldg((const float2*)(p2 + 8));
                b1f[st][t][0] = cvt2(lo1.y, lo1.x);
                b1f[st][t][1] = cvt2(hi1.y, hi1.x);
                b2f[st][t][0] = cvt2(lo2.y, lo2.x);
                b2f[st][t][1] = cvt2(hi2.y, hi2.x);
            }
        }
    }
    __syncthreads();                              // sdet visible

    // --- c phase: half 0 -> A1 (k 0..15), half 1 -> A2 (k 16..31) ---
    {
        const bool is64 = ((sdet[0] | sdet[1] | sdet[2] | sdet[3]) == 0);
        const int  half = tid >> 6;
        const int  t    = tid & 63;
        const int  i    = ttile * TTOK + t;
        const int  tok  = is64 ? xw[2 * i] : xw[i];
        if (half == 0) stok[t] = tok;
        const int s = i & (SLEN - 1);
        const float* W = (s < SPLITL) ? Wi : Wt;
        const float* b = (s < SPLITL) ? bi : bt;
        float l0 = W[tok] + b[0];
        float l1 = W[VDIM + tok] + b[1];
        float w0 = 1.0f / (1.0f + expf(l1 - l0));
        float sA = half ? (SCALE - w0 * SCALE) : (w0 * SCALE);
        const float* Am = half ? A2 : A1;
        float c[16];
#pragma unroll
        for (int r = 0; r < 16; r++) c[r] = sA * Am[(size_t)r * VDIM + tok];
        uint32_t u[8];
#pragma unroll
        for (int j = 0; j < 8; j++) u[j] = cvt2(c[2 * j + 1], c[2 * j]);
        uint4* dst = (uint4*)(cA + t * CROW + half * 32);
        dst[0] = make_uint4(u[0], u[1], u[2], u[3]);
        dst[1] = make_uint4(u[4], u[5], u[6], u[7]);
    }
    __syncthreads();                              // cA + stok visible

    // --- main: 4 m-tiles of 16 tokens ---
    const uint32_t cAu   = s2u(cA);
    const size_t   obase = (size_t)(ttile * TTOK) * DDIM;
    const int      c4    = 4 * (lane & 3);        // lane's 4 contiguous cols (per st)

#pragma unroll 1
    for (int mt = 0; mt < 4; mt++) {
        const int tr0  = mt * 16 + (lane >> 2);
        const int tr1  = tr0 + 8;
        const int tok0 = stok[tr0];
        const int tok1 = stok[tr1];

        // base prefetch: 8 LDG.128 per lane-pairing, latency covered by LDSM+MMA
        float4 bs0[4], bs1[4];
        {
            const float* e0 = emb + (size_t)tok0 * DDIM + dwarp + c4;
            const float* e1 = emb + (size_t)tok1 * DDIM + dwarp + c4;
#pragma unroll
            for (int st = 0; st < 4; st++) {
                bs0[st] = __ldg((const float4*)(e0 + st * 16));
                bs1[st] = __ldg((const float4*)(e1 + st * 16));
            }
        }

        // A fragments: 2x ldmatrix.x4 (k-step 0 at +0, k-step 1 at +32B)
        uint32_t a0, a1, a2, a3, a4, a5, a6, a7;
        {
            uint32_t ad = cAu + (uint32_t)(mt * 16 + (lane & 15)) * CROW
                        + ((lane >> 4) << 4);
            asm volatile("ldmatrix.sync.aligned.m8n8.x4.shared.b16 {%0,%1,%2,%3}, [%4];"
                         : "=r"(a0), "=r"(a1), "=r"(a2), "=r"(a3) : "r"(ad));
            asm volatile("ldmatrix.sync.aligned.m8n8.x4.shared.b16 {%0,%1,%2,%3}, [%4];"
                         : "=r"(a4), "=r"(a5), "=r"(a6), "=r"(a7) : "r"(ad + 32));
        }

        // 4 super-tiles: tiles X and Y (2 mma each), fused float4 epilogue
#pragma unroll
        for (int st = 0; st < 4; st++) {
            float x0 = 0.f, x1 = 0.f, x2 = 0.f, x3 = 0.f;
            float y0 = 0.f, y1 = 0.f, y2 = 0.f, y3 = 0.f;
            mma16816(x0, x1, x2, x3, a0, a1, a2, a3, b1f[st][0][0], b1f[st][0][1]);
            mma16816(x0, x1, x2, x3, a4, a5, a6, a7, b2f[st][0][0], b2f[st][0][1]);
            mma16816(y0, y1, y2, y3, a0, a1, a2, a3, b1f[st][1][0], b1f[st][1][1]);
            mma16816(y0, y1, y2, y3, a4, a5, a6, a7, b2f[st][1][0], b2f[st][1][1]);
            float4 o0, o1;
            o0.x = bs0[st].x + x0;  o0.y = bs0[st].y + x1;
            o0.z = bs0[st].z + y0;  o0.w = bs0[st].w + y1;
            o1.x = bs1[st].x + x2;  o1.y = bs1[st].y + x3;
            o1.z = bs1[st].z + y2;  o1.w = bs1[st].w + y3;
            const size_t oc = dwarp + c4 + st * 16;
            __stcs((float4*)(out + obase + (size_t)tr0 * DDIM + oc), o0);
            __stcs((float4*)(out + obase + (size_t)tr1 * DDIM + oc), o1);
        }
    }
}

// ---------------------------------------------------------------------------
extern "C" void kernel_launch(void* const* d_in, const int* in_sizes, int n_in,
                              void* d_out, int out_size) {
    const int*   x   = (const int*)d_in[0];
    const float* emb = (const float*)d_in[1];
    const float* A1  = (const float*)d_in[2];
    const float* B1  = (const float*)d_in[3];
    const float* A2  = (const float*)d_in[4];
    const float* B2  = (const float*)d_in[5];
    const float* Wi  = (const float*)d_in[6];
    const float* bi  = (const float*)d_in[7];
    const float* Wt  = (const float*)d_in[8];
    const float* bt  = (const float*)d_in[9];
    float* out = (float*)d_out;

    fused_k<<<dim3(TOKS / TTOK, DDIM / TD), 128>>>(
        x, emb, A1, B1, A2, B2, Wi, bi, Wt, bt, out);
}

// round 11
// speedup vs baseline: 1.8691x; 1.0087x over previous
#include <cuda_runtime.h>
#include <cuda_bf16.h>
#include <cstdint>

// B=8, S=512, V=32000, D=4096, r=16, E=4
#define TOKS   4096
#define SLEN   512
#define SPLITL 32
#define DDIM   4096
#define VDIM   32000
#define SCALE  2.0f   // lora_alpha / r

#define TTOK   64     // tokens per CTA (4 m-tiles of 16)
#define TD     256    // d per CTA (4 warps * 64)
#define CROW   80     // c-tile row stride in bytes (16B-aligned, LDSM conflict-free)

__device__ __forceinline__ uint32_t s2u(const void* p) {
    uint32_t a;
    asm("{ .reg .u64 t; cvta.to.shared.u64 t, %1; cvt.u32.u64 %0, t; }"
        : "=r"(a) : "l"(p));
    return a;
}
// pack two f32 into bf16x2: lo -> low 16 bits, hi -> high
__device__ __forceinline__ uint32_t cvt2(float hi, float lo) {
    uint32_t r;
    asm("cvt.rn.bf16x2.f32 %0, %1, %2;" : "=r"(r) : "f"(hi), "f"(lo));
    return r;
}
__device__ __forceinline__ void mma16816(
    float& d0, float& d1, float& d2, float& d3,
    uint32_t a0, uint32_t a1, uint32_t a2, uint32_t a3,
    uint32_t b0, uint32_t b1)
{
    asm volatile(
        "mma.sync.aligned.m16n8k16.row.col.f32.bf16.bf16.f32 "
        "{%0,%1,%2,%3}, {%4,%5,%6,%7}, {%8,%9}, {%0,%1,%2,%3};"
        : "+f"(d0), "+f"(d1), "+f"(d2), "+f"(d3)
        : "r"(a0), "r"(a1), "r"(a2), "r"(a3), "r"(b0), "r"(b1));
}

// ---------------------------------------------------------------------------
// Grid (64 token-tiles, 16 d-tiles) = 1024 CTAs, 128 threads (4 warps), 3/SM.
// delta = C[64x32]·Wcat[32x256]^T via mma.sync m16n8k16 bf16 (f32 accum).
// B-fragment column remap pairs mma tiles (X,Y) over 16 global cols:
//   gX(c) = 4*(c>>1) + (c&1), gY(c) = gX(c) + 2
// so each lane's X∪Y outputs are 4 CONTIGUOUS floats -> float4 gather/store.
// Base gather is DOUBLE-BUFFERED across m-tiles: m-tile t+1's 8 LDG.128 are
// issued before m-tile t's LDSM/MMA/epilogue, so the scoreboard wait sits a
// full iteration (~400+ cyc) behind the issue -> DRAM latency covered even
// at 12 warps/SM.
// c-phase: threads 0-63 -> A1*(w0*SCALE) (k 0..15), 64-127 -> A2 (k 16..31).
// int64/int32 x detection: odd words of first 256 x-words all zero <=> int64.
// ---------------------------------------------------------------------------
__global__ __launch_bounds__(128, 3) void fused_k(
    const int*   __restrict__ xw,
    const float* __restrict__ emb,
    const float* __restrict__ A1, const float* __restrict__ B1,
    const float* __restrict__ A2, const float* __restrict__ B2,
    const float* __restrict__ Wi, const float* __restrict__ bi,
    const float* __restrict__ Wt, const float* __restrict__ bt,
    float* __restrict__ out)
{
    __shared__ __align__(16) unsigned char cA[TTOK * CROW];  // c tile, bf16
    __shared__ int      stok[TTOK];
    __shared__ unsigned sdet[4];

    const int tid   = threadIdx.x;
    const int lane  = tid & 31;
    const int w     = tid >> 5;
    const int ttile = blockIdx.x;
    const int dwarp = blockIdx.y * TD + w * 64;   // this warp's 64 d-columns

    // --- dtype detect ---
    {
        int hiw = xw[2 * tid + 1];                // words 1..255, in-bounds both ways
        unsigned ball = __ballot_sync(0xffffffffu, hiw != 0);
        if (lane == 0) sdet[w] = ball;
    }

    // --- B fragments with remapped columns ---
    // lane's fragment column n = lane>>2; tile (st, t): gcol = st*16 + 4*(n>>1) + 2*t + (n&1)
    uint32_t b1f[4][2][2], b2f[4][2][2];
    {
        const int n  = lane >> 2;
        const int kk = 2 * (lane & 3);
#pragma unroll
        for (int st = 0; st < 4; st++) {
#pragma unroll
            for (int t = 0; t < 2; t++) {
                const int gcol = dwarp + st * 16 + 4 * (n >> 1) + 2 * t + (n & 1);
                const float* p1 = B1 + (size_t)gcol * 16 + kk;
                const float* p2 = B2 + (size_t)gcol * 16 + kk;
                float2 lo1 = __ldg((const float2*)p1);
                float2 hi1 = __ldg((const float2*)(p1 + 8));
                float2 lo2 = __ldg((const float2*)p2);
                float2 hi2 = __ldg((const float2*)(p2 + 8));
                b1f[st][t][0] = cvt2(lo1.y, lo1.x);
                b1f[st][t][1] = cvt2(hi1.y, hi1.x);
                b2f[st][t][0] = cvt2(lo2.y, lo2.x);
                b2f[st][t][1] = cvt2(hi2.y, hi2.x);
            }
        }
    }
    __syncthreads();                              // sdet visible

    // --- c phase: half 0 -> A1 (k 0..15), half 1 -> A2 (k 16..31) ---
    {
        const bool is64 = ((sdet[0] | sdet[1] | sdet[2] | sdet[3]) == 0);
        const int  half = tid >> 6;
        const int  t    = tid & 63;
        const int  i    = ttile * TTOK + t;
        const int  tok  = is64 ? xw[2 * i] : xw[i];
        if (half == 0) stok[t] = tok;
        const int s = i & (SLEN - 1);
        const float* W = (s < SPLITL) ? Wi : Wt;
        const float* b = (s < SPLITL) ? bi : bt;
        float l0 = W[tok] + b[0];
        float l1 = W[VDIM + tok] + b[1];
        float w0 = 1.0f / (1.0f + expf(l1 - l0));
        float sA = half ? (SCALE - w0 * SCALE) : (w0 * SCALE);
        const float* Am = half ? A2 : A1;
        float c[16];
#pragma unroll
        for (int r = 0; r < 16; r++) c[r] = sA * Am[(size_t)r * VDIM + tok];
        uint32_t u[8];
#pragma unroll
        for (int j = 0; j < 8; j++) u[j] = cvt2(c[2 * j + 1], c[2 * j]);
        uint4* dst = (uint4*)(cA + t * CROW + half * 32);
        dst[0] = make_uint4(u[0], u[1], u[2], u[3]);
        dst[1] = make_uint4(u[4], u[5], u[6], u[7]);
    }
    __syncthreads();                              // cA + stok visible

    // --- main: 4 m-tiles of 16 tokens, gather double-buffered across tiles ---
    const uint32_t cAu   = s2u(cA);
    const size_t   obase = (size_t)(ttile * TTOK) * DDIM;
    const int      c4    = 4 * (lane & 3);        // lane's 4 contiguous cols (per st)

    float4 bs0[2][4], bs1[2][4];                  // [buffer][super-tile]

    // preload m-tile 0
    {
        const float* e0 = emb + (size_t)stok[lane >> 2] * DDIM + dwarp + c4;
        const float* e1 = emb + (size_t)stok[(lane >> 2) + 8] * DDIM + dwarp + c4;
#pragma unroll
        for (int st = 0; st < 4; st++) {
            bs0[0][st] = __ldg((const float4*)(e0 + st * 16));
            bs1[0][st] = __ldg((const float4*)(e1 + st * 16));
        }
    }

#pragma unroll
    for (int mt = 0; mt < 4; mt++) {
        const int cur = mt & 1;

        // issue next m-tile's gather FIRST (full iteration of cover ahead)
        if (mt + 1 < 4) {
            const int nxt  = (mt + 1) & 1;
            const int tr0n = (mt + 1) * 16 + (lane >> 2);
            const float* e0 = emb + (size_t)stok[tr0n] * DDIM + dwarp + c4;
            const float* e1 = emb + (size_t)stok[tr0n + 8] * DDIM + dwarp + c4;
#pragma unroll
            for (int st = 0; st < 4; st++) {
                bs0[nxt][st] = __ldg((const float4*)(e0 + st * 16));
                bs1[nxt][st] = __ldg((const float4*)(e1 + st * 16));
            }
        }

        // A fragments: 2x ldmatrix.x4 (k-step 0 at +0, k-step 1 at +32B)
        uint32_t a0, a1, a2, a3, a4, a5, a6, a7;
        {
            uint32_t ad = cAu + (uint32_t)(mt * 16 + (lane & 15)) * CROW
                        + ((lane >> 4) << 4);
            asm volatile("ldmatrix.sync.aligned.m8n8.x4.shared.b16 {%0,%1,%2,%3}, [%4];"
                         : "=r"(a0), "=r"(a1), "=r"(a2), "=r"(a3) : "r"(ad));
            asm volatile("ldmatrix.sync.aligned.m8n8.x4.shared.b16 {%0,%1,%2,%3}, [%4];"
                         : "=r"(a4), "=r"(a5), "=r"(a6), "=r"(a7) : "r"(ad + 32));
        }

        const int tr0 = mt * 16 + (lane >> 2);
        const int tr1 = tr0 + 8;

        // 4 super-tiles: tiles X and Y (2 mma each), fused float4 epilogue
#pragma unroll
        for (int st = 0; st < 4; st++) {
            float x0 = 0.f, x1 = 0.f, x2 = 0.f, x3 = 0.f;
            float y0 = 0.f, y1 = 0.f, y2 = 0.f, y3 = 0.f;
            mma16816(x0, x1, x2, x3, a0, a1, a2, a3, b1f[st][0][0], b1f[st][0][1]);
            mma16816(x0, x1, x2, x3, a4, a5, a6, a7, b2f[st][0][0], b2f[st][0][1]);
            mma16816(y0, y1, y2, y3, a0, a1, a2, a3, b1f[st][1][0], b1f[st][1][1]);
            mma16816(y0, y1, y2, y3, a4, a5, a6, a7, b2f[st][1][0], b2f[st][1][1]);
            float4 o0, o1;
            o0.x = bs0[cur][st].x + x0;  o0.y = bs0[cur][st].y + x1;
            o0.z = bs0[cur][st].z + y0;  o0.w = bs0[cur][st].w + y1;
            o1.x = bs1[cur][st].x + x2;  o1.y = bs1[cur][st].y + x3;
            o1.z = bs1[cur][st].z + y2;  o1.w = bs1[cur][st].w + y3;
            const size_t oc = dwarp + c4 + st * 16;
            __stcs((float4*)(out + obase + (size_t)tr0 * DDIM + oc), o0);
            __stcs((float4*)(out + obase + (size_t)tr1 * DDIM + oc), o1);
        }
    }
}

// ---------------------------------------------------------------------------
extern "C" void kernel_launch(void* const* d_in, const int* in_sizes, int n_in,
                              void* d_out, int out_size) {
    const int*   x   = (const int*)d_in[0];
    const float* emb = (const float*)d_in[1];
    const float* A1  = (const float*)d_in[2];
    const float* B1  = (const float*)d_in[3];
    const float* A2  = (const float*)d_in[4];
    const float* B2  = (const float*)d_in[5];
    const float* Wi  = (const float*)d_in[6];
    const float* bi  = (const float*)d_in[7];
    const float* Wt  = (const float*)d_in[8];
    const float* bt  = (const float*)d_in[9];
    float* out = (float*)d_out;

    fused_k<<<dim3(TOKS / TTOK, DDIM / TD), 128>>>(
        x, emb, A1, B1, A2, B2, Wi, bi, Wt, bt, out);
}

// round 12
// speedup vs baseline: 2.0166x; 1.0789x over previous
#include <cuda_runtime.h>
#include <cuda_bf16.h>
#include <cstdint>

// B=8, S=512, V=32000, D=4096, r=16, E=4
#define TOKS   4096
#define SLEN   512
#define SPLITL 32
#define DDIM   4096
#define VDIM   32000
#define SCALE  2.0f   // lora_alpha / r

#define TTOK   64     // tokens per CTA (4 m-tiles of 16)
#define TD     256    // d per CTA (4 warps * 64)
#define CROW   80     // c-tile row stride in bytes (16B-aligned, LDSM conflict-free)

__device__ uint4 g_C[TOKS * 4];   // C[tok][32] bf16 = 64B/row = 4 uint4
__device__ int   g_tok[TOKS];     // decoded token ids

__device__ __forceinline__ uint32_t s2u(const void* p) {
    uint32_t a;
    asm("{ .reg .u64 t; cvta.to.shared.u64 t, %1; cvt.u32.u64 %0, t; }"
        : "=r"(a) : "l"(p));
    return a;
}
// pack two f32 into bf16x2: lo -> low 16 bits, hi -> high
__device__ __forceinline__ uint32_t cvt2(float hi, float lo) {
    uint32_t r;
    asm("cvt.rn.bf16x2.f32 %0, %1, %2;" : "=r"(r) : "f"(hi), "f"(lo));
    return r;
}
__device__ __forceinline__ void mma16816(
    float& d0, float& d1, float& d2, float& d3,
    uint32_t a0, uint32_t a1, uint32_t a2, uint32_t a3,
    uint32_t b0, uint32_t b1)
{
    asm volatile(
        "mma.sync.aligned.m16n8k16.row.col.f32.bf16.bf16.f32 "
        "{%0,%1,%2,%3}, {%4,%5,%6,%7}, {%8,%9}, {%0,%1,%2,%3};"
        : "+f"(d0), "+f"(d1), "+f"(d2), "+f"(d3)
        : "r"(a0), "r"(a1), "r"(a2), "r"(a3), "r"(b0), "r"(b1));
}

// ---------------------------------------------------------------------------
// Kernel 1: producer. 32 CTAs x 256 threads; thread = (token, half).
// Computes c[tok][k] = router_weight * SCALE * A{1,2}[k, tok] (bf16) ONCE and
// stores to g_C — removing the 16x-redundant scattered A-gather from the main
// kernel. Also decodes token ids (int64 vs int32: odd words of the first 512
// x-words are all zero iff int64) into g_tok.
// ---------------------------------------------------------------------------
__global__ __launch_bounds__(256) void c_k(
    const int*   __restrict__ xw,
    const float* __restrict__ A1, const float* __restrict__ A2,
    const float* __restrict__ Wi, const float* __restrict__ bi,
    const float* __restrict__ Wt, const float* __restrict__ bt)
{
    __shared__ unsigned sdet[8];
    const int tid = threadIdx.x;

    {
        int hiw = xw[2 * tid + 1];                 // words 1..511 odd, in-bounds both ways
        unsigned ball = __ballot_sync(0xffffffffu, hiw != 0);
        if ((tid & 31) == 0) sdet[tid >> 5] = ball;
    }
    __syncthreads();
    unsigned det = 0;
#pragma unroll
    for (int j = 0; j < 8; j++) det |= sdet[j];
    const bool is64 = (det == 0);

    const int gid  = blockIdx.x * 256 + tid;
    const int i    = gid >> 1;                     // token index
    const int half = gid & 1;
    const int tok  = is64 ? xw[2 * i] : xw[i];
    if (half == 0) g_tok[i] = tok;

    const int s = i & (SLEN - 1);
    const float* W = (s < SPLITL) ? Wi : Wt;
    const float* b = (s < SPLITL) ? bi : bt;
    float l0 = W[tok] + b[0];
    float l1 = W[VDIM + tok] + b[1];
    float w0 = 1.0f / (1.0f + expf(l1 - l0));
    float sA = half ? (SCALE - w0 * SCALE) : (w0 * SCALE);
    const float* Am = half ? A2 : A1;

    float c[16];
#pragma unroll
    for (int r = 0; r < 16; r++) c[r] = sA * Am[(size_t)r * VDIM + tok];
    uint32_t u[8];
#pragma unroll
    for (int j = 0; j < 8; j++) u[j] = cvt2(c[2 * j + 1], c[2 * j]);
    g_C[i * 4 + half * 2 + 0] = make_uint4(u[0], u[1], u[2], u[3]);
    g_C[i * 4 + half * 2 + 1] = make_uint4(u[4], u[5], u[6], u[7]);
}

// ---------------------------------------------------------------------------
// Kernel 2: main. Grid (64 token-tiles, 16 d-tiles) = 1024 CTAs, 4 warps, 4/SM.
// delta = C[64x32]·Wcat[32x256]^T via mma.sync m16n8k16 bf16 (f32 accum).
// C tile comes from g_C (coalesced 4KB LDG.128) into smem for ldmatrix.
// B-fragment column remap pairs mma tiles (X,Y): gX(c)=4*(c>>1)+(c&1),
// gY=gX+2, so each lane's X∪Y outputs are 4 contiguous floats -> float4
// gather/store epilogue (8 LDG.128 + 8 STG.128 per warp-mtile).
// ---------------------------------------------------------------------------
__global__ __launch_bounds__(128, 4) void fused_k(
    const float* __restrict__ emb,
    const float* __restrict__ B1, const float* __restrict__ B2,
    float* __restrict__ out)
{
    __shared__ __align__(16) unsigned char cA[TTOK * CROW];  // c tile, bf16
    __shared__ int stok[TTOK];

    const int tid   = threadIdx.x;
    const int lane  = tid & 31;
    const int w     = tid >> 5;
    const int ttile = blockIdx.x;
    const int dwarp = blockIdx.y * TD + w * 64;   // this warp's 64 d-columns

    // --- C tile: coalesced load from g_C into smem (80B rows) ---
    {
        const int row = tid >> 1;
        const int hf  = tid & 1;
        const uint4* src = g_C + (size_t)(ttile * TTOK + row) * 4 + hf * 2;
        uint4 v0 = src[0];
        uint4 v1 = src[1];
        uint4* dst = (uint4*)(cA + row * CROW + hf * 32);
        dst[0] = v0;
        dst[1] = v1;
    }
    if (tid < TTOK) stok[tid] = g_tok[ttile * TTOK + tid];

    // --- B fragments with remapped columns (L2-resident) ---
    uint32_t b1f[4][2][2], b2f[4][2][2];
    {
        const int n  = lane >> 2;
        const int kk = 2 * (lane & 3);
#pragma unroll
        for (int st = 0; st < 4; st++) {
#pragma unroll
            for (int t = 0; t < 2; t++) {
                const int gcol = dwarp + st * 16 + 4 * (n >> 1) + 2 * t + (n & 1);
                const float* p1 = B1 + (size_t)gcol * 16 + kk;
                const float* p2 = B2 + (size_t)gcol * 16 + kk;
                float2 lo1 = __ldg((const float2*)p1);
                float2 hi1 = __ldg((const float2*)(p1 + 8));
                float2 lo2 = __ldg((const float2*)p2);
                float2 hi2 = __ldg((const float2*)(p2 + 8));
                b1f[st][t][0] = cvt2(lo1.y, lo1.x);
                b1f[st][t][1] = cvt2(hi1.y, hi1.x);
                b2f[st][t][0] = cvt2(lo2.y, lo2.x);
                b2f[st][t][1] = cvt2(hi2.y, hi2.x);
            }
        }
    }
    __syncthreads();                              // cA + stok visible

    // --- main: 4 m-tiles of 16 tokens ---
    const uint32_t cAu   = s2u(cA);
    const size_t   obase = (size_t)(ttile * TTOK) * DDIM;
    const int      c4    = 4 * (lane & 3);        // lane's 4 contiguous cols (per st)

#pragma unroll 1
    for (int mt = 0; mt < 4; mt++) {
        const int tr0  = mt * 16 + (lane >> 2);
        const int tr1  = tr0 + 8;
        const int tok0 = stok[tr0];
        const int tok1 = stok[tr1];

        // base prefetch: 8 LDG.128, latency covered by LDSM+MMA below
        float4 bs0[4], bs1[4];
        {
            const float* e0 = emb + (size_t)tok0 * DDIM + dwarp + c4;
            const float* e1 = emb + (size_t)tok1 * DDIM + dwarp + c4;
#pragma unroll
            for (int st = 0; st < 4; st++) {
                bs0[st] = __ldg((const float4*)(e0 + st * 16));
                bs1[st] = __ldg((const float4*)(e1 + st * 16));
            }
        }

        // A fragments: 2x ldmatrix.x4 (k-step 0 at +0, k-step 1 at +32B)
        uint32_t a0, a1, a2, a3, a4, a5, a6, a7;
        {
            uint32_t ad = cAu + (uint32_t)(mt * 16 + (lane & 15)) * CROW
                        + ((lane >> 4) << 4);
            asm volatile("ldmatrix.sync.aligned.m8n8.x4.shared.b16 {%0,%1,%2,%3}, [%4];"
                         : "=r"(a0), "=r"(a1), "=r"(a2), "=r"(a3) : "r"(ad));
            asm volatile("ldmatrix.sync.aligned.m8n8.x4.shared.b16 {%0,%1,%2,%3}, [%4];"
                         : "=r"(a4), "=r"(a5), "=r"(a6), "=r"(a7) : "r"(ad + 32));
        }

        // 4 super-tiles: tiles X and Y (2 mma each), fused float4 epilogue
#pragma unroll
        for (int st = 0; st < 4; st++) {
            float x0 = 0.f, x1 = 0.f, x2 = 0.f, x3 = 0.f;
            float y0 = 0.f, y1 = 0.f, y2 = 0.f, y3 = 0.f;
            mma16816(x0, x1, x2, x3, a0, a1, a2, a3, b1f[st][0][0], b1f[st][0][1]);
            mma16816(x0, x1, x2, x3, a4, a5, a6, a7, b2f[st][0][0], b2f[st][0][1]);
            mma16816(y0, y1, y2, y3, a0, a1, a2, a3, b1f[st][1][0], b1f[st][1][1]);
            mma16816(y0, y1, y2, y3, a4, a5, a6, a7, b2f[st][1][0], b2f[st][1][1]);
            float4 o0, o1;
            o0.x = bs0[st].x + x0;  o0.y = bs0[st].y + x1;
            o0.z = bs0[st].z + y0;  o0.w = bs0[st].w + y1;
            o1.x = bs1[st].x + x2;  o1.y = bs1[st].y + x3;
            o1.z = bs1[st].z + y2;  o1.w = bs1[st].w + y3;
            const size_t oc = dwarp + c4 + st * 16;
            __stcs((float4*)(out + obase + (size_t)tr0 * DDIM + oc), o0);
            __stcs((float4*)(out + obase + (size_t)tr1 * DDIM + oc), o1);
        }
    }
}

// ---------------------------------------------------------------------------
extern "C" void kernel_launch(void* const* d_in, const int* in_sizes, int n_in,
                              void* d_out, int out_size) {
    const int*   x   = (const int*)d_in[0];
    const float* emb = (const float*)d_in[1];
    const float* A1  = (const float*)d_in[2];
    const float* B1  = (const float*)d_in[3];
    const float* A2  = (const float*)d_in[4];
    const float* B2  = (const float*)d_in[5];
    const float* Wi  = (const float*)d_in[6];
    const float* bi  = (const float*)d_in[7];
    const float* Wt  = (const float*)d_in[8];
    const float* bt  = (const float*)d_in[9];
    float* out = (float*)d_out;

    c_k<<<TOKS * 2 / 256, 256>>>(x, A1, A2, Wi, bi, Wt, bt);
    fused_k<<<dim3(TOKS / TTOK, DDIM / TD), 128>>>(emb, B1, B2, out);
}